// round 8
// baseline (speedup 1.0000x reference)
#include <cuda_runtime.h>
#include <math.h>

#define BB   16
#define NN   4096
#define EE   65536
#define HH   512
#define MM1  1024
#define MM2  32768

// ---- device scratch. NEVER named in host code (host shadows + GB300 ATS
// would silently write host memory and trip the harness mem guard). --------
__device__ int   g_deg[NN];
__device__ int   g_off[NN + 1];
__device__ int   g_cur[NN];
__device__ int   g_src[EE];
__device__ float g_hA [(size_t)BB * NN * 32];   // 8 MB
__device__ float g_hB [(size_t)BB * NN * 32];   // 8 MB
__device__ float g_w  [(size_t)BB * EE];        // 4 MB edge softmax weights
__device__ float g_as0[(size_t)BB * NN], g_ad0[(size_t)BB * NN];
__device__ float g_as1[(size_t)BB * NN], g_ad1[(size_t)BB * NN];
__device__ float g_ws [(size_t)BB * NN];        // self weight
__device__ float g_wn [(size_t)BB * NN];        // 1/wsum
__device__ float g_gi [(size_t)BB * 3 * HH];
__device__ float g_gh [(size_t)BB * 3 * HH];
__device__ float g_nh [(size_t)BB * HH];
__device__ float g_o1 [(size_t)BB * MM1];

// ---------------- CSR build ------------------------------------------------
__global__ void k_zero_deg(int n) {
    int i = blockIdx.x * blockDim.x + threadIdx.x;
    if (i < n) g_deg[i] = 0;
}
__global__ void k_hist(const int* __restrict__ ei, int n) {
    int i = blockIdx.x * blockDim.x + threadIdx.x;
    if (i < n) atomicAdd(&g_deg[ei[EE + i]], 1);
}
__global__ void k_scan(int active) {
    if (!active) return;
    __shared__ int s[1024];
    int tid = threadIdx.x;
    int b4 = tid * 4;
    int v0 = g_deg[b4], v1 = g_deg[b4 + 1], v2 = g_deg[b4 + 2], v3 = g_deg[b4 + 3];
    int sum = v0 + v1 + v2 + v3;
    s[tid] = sum;
    __syncthreads();
    for (int o = 1; o < 1024; o <<= 1) {
        int t = (tid >= o) ? s[tid - o] : 0;
        __syncthreads();
        s[tid] += t;
        __syncthreads();
    }
    int excl = s[tid] - sum;
    int o0 = excl, o1 = excl + v0, o2 = o1 + v1, o3 = o2 + v2;
    g_off[b4] = o0; g_off[b4 + 1] = o1; g_off[b4 + 2] = o2; g_off[b4 + 3] = o3;
    g_cur[b4] = o0; g_cur[b4 + 1] = o1; g_cur[b4 + 2] = o2; g_cur[b4 + 3] = o3;
    if (tid == 1023) g_off[NN] = s[1023];
}
__global__ void k_scatter(const int* __restrict__ ei, int n) {
    int i = blockIdx.x * blockDim.x + threadIdx.x;
    if (i < n) {
        int d = ei[EE + i];
        int pos = atomicAdd(&g_cur[d], 1);
        g_src[pos] = ei[i];
    }
}

__device__ __forceinline__ float lrelu(float v) { return v >= 0.f ? v : 0.2f * v; }

// ---- layer-0 features, all batches: warp per (b,n), lane = feature --------
__global__ void k_feat3(const float* __restrict__ svp,
                        const float* __restrict__ W0,
                        const float* __restrict__ a0s,
                        const float* __restrict__ a0d,
                        int nwork) {
    int gw = (blockIdx.x * blockDim.x + threadIdx.x) >> 5;
    int lane = threadIdx.x & 31;
    if (gw >= nwork) return;
    const float* xv = svp + (size_t)gw * 3;
    float v0 = xv[0], v1 = xv[1], v2 = xv[2];
    float hv = W0[lane * 3] * v0 + W0[lane * 3 + 1] * v1 + W0[lane * 3 + 2] * v2;
    g_hA[(size_t)gw * 32 + lane] = hv;
    float ps = hv * a0s[lane];
    float pd = hv * a0d[lane];
#pragma unroll
    for (int o = 16; o > 0; o >>= 1) {
        ps += __shfl_xor_sync(0xffffffffu, ps, o);
        pd += __shfl_xor_sync(0xffffffffu, pd, o);
    }
    if (lane == 0) { g_as0[gw] = ps; g_ad0[gw] = pd; }
}

// ---- edge softmax weights (LAYER selects as0/ad0 vs as1/ad1) --------------
template <int LAYER>
__global__ void k_wgt(int nwork) {
    int gw = (blockIdx.x * blockDim.x + threadIdx.x) >> 5;
    int lane = threadIdx.x & 31;
    if (gw >= nwork) return;
    int b = gw >> 12;
    int d = gw & (NN - 1);
    const float* as_ = (LAYER == 0) ? g_as0 : g_as1;
    const float* ad_ = (LAYER == 0) ? g_ad0 : g_ad1;
    const float* asb = as_ + (size_t)b * NN;
    float add = ad_[(size_t)b * NN + d];
    int beg = g_off[d], end = g_off[d + 1];

    float e_self = lrelu(asb[d] + add);
    float m = e_self;
    for (int i = beg + lane; i < end; i += 32)
        m = fmaxf(m, lrelu(asb[g_src[i]] + add));
#pragma unroll
    for (int o = 16; o > 0; o >>= 1) m = fmaxf(m, __shfl_xor_sync(0xffffffffu, m, o));
    float wsum = 0.f;
    float* wb = g_w + (size_t)b * EE;
    for (int i = beg + lane; i < end; i += 32) {
        float w = expf(lrelu(asb[g_src[i]] + add) - m);
        wb[i] = w;
        wsum += w;
    }
#pragma unroll
    for (int o = 16; o > 0; o >>= 1) wsum += __shfl_xor_sync(0xffffffffu, wsum, o);
    float wself = expf(e_self - m);
    wsum += wself;
    if (lane == 0) {
        g_ws[gw] = wself;
        g_wn[gw] = 1.f / wsum;
    }
}

// ---- aggregate layer 0 (reads g_w/g_hA) fused with layer-1 transform ------
__global__ void k_agg0_feat1(const float* __restrict__ b0,
                             const float* __restrict__ W1,
                             const float* __restrict__ a1s,
                             const float* __restrict__ a1d,
                             int nwork) {
    int gw = (blockIdx.x * blockDim.x + threadIdx.x) >> 5;
    int lane = threadIdx.x & 31;
    if (gw >= nwork) return;
    int b = gw >> 12;
    int d = gw & (NN - 1);
    int beg = g_off[d], end = g_off[d + 1];
    const float* hb = g_hA + (size_t)b * NN * 32;
    const float* wb = g_w + (size_t)b * EE;

    float acc = g_ws[gw] * hb[(size_t)d * 32 + lane];
    for (int j = beg; j < end; j++)
        acc += wb[j] * hb[(size_t)g_src[j] * 32 + lane];
    float gat = acc * g_wn[gw] + b0[lane];

    float hv = 0.f;
#pragma unroll
    for (int k = 0; k < 32; k++) {
        float gk = __shfl_sync(0xffffffffu, gat, k);
        hv += W1[lane * 32 + k] * gk;
    }
    g_hB[(size_t)gw * 32 + lane] = hv;
    float ps = hv * a1s[lane];
    float pd = hv * a1d[lane];
#pragma unroll
    for (int o = 16; o > 0; o >>= 1) {
        ps += __shfl_xor_sync(0xffffffffu, ps, o);
        pd += __shfl_xor_sync(0xffffffffu, pd, o);
    }
    if (lane == 0) { g_as1[gw] = ps; g_ad1[gw] = pd; }
}

// ---- aggregate layer 1 fused with GAT slice of output projection ----------
__global__ void k_agg1_out(const float* __restrict__ b1,
                           const float* __restrict__ wo,   // [3 x 40]
                           float* __restrict__ out,
                           int nwork) {
    int gw = (blockIdx.x * blockDim.x + threadIdx.x) >> 5;
    int lane = threadIdx.x & 31;
    if (gw >= nwork) return;
    int b = gw >> 12;
    int d = gw & (NN - 1);
    int beg = g_off[d], end = g_off[d + 1];
    const float* hb = g_hB + (size_t)b * NN * 32;
    const float* wb = g_w + (size_t)b * EE;

    float acc = g_ws[gw] * hb[(size_t)d * 32 + lane];
    for (int j = beg; j < end; j++)
        acc += wb[j] * hb[(size_t)g_src[j] * 32 + lane];
    float gat = acc * g_wn[gw] + b1[lane];

    float s0 = gat * wo[8 + lane];
    float s1 = gat * wo[48 + lane];
    float s2 = gat * wo[88 + lane];
#pragma unroll
    for (int o = 16; o > 0; o >>= 1) {
        s0 += __shfl_xor_sync(0xffffffffu, s0, o);
        s1 += __shfl_xor_sync(0xffffffffu, s1, o);
        s2 += __shfl_xor_sync(0xffffffffu, s2, o);
    }
    if (lane == 0) {
        size_t base = (size_t)gw * 3;
        out[base + 0] += s0;      // sequential launch order: sole writer now
        out[base + 1] += s1;
        out[base + 2] += s2;
    }
}

// ---------------- small GEMMs: scratch chosen by selectors ------------------
// asel: 0 = external A arg, 1 = g_nh. csel: 0 = g_gi, 1 = g_gh, 2 = g_o1.
template <bool EPI>
__global__ void k_rowgemm(const float* __restrict__ Aext, int asel, int csel,
                          const float* __restrict__ W,
                          const float* __restrict__ bias,
                          const float* __restrict__ pr,
                          const float* __restrict__ bg,
                          const float* __restrict__ bb,
                          int M, int K) {
    const float* A = (asel == 1) ? (const float*)g_nh : Aext;
    float* C = (csel == 0) ? g_gi : (csel == 1) ? g_gh : g_o1;
    extern __shared__ float sA[];
    for (int i = threadIdx.x; i < 16 * K; i += blockDim.x) sA[i] = A[i];
    __syncthreads();
    int row = (blockIdx.x * blockDim.x + threadIdx.x) >> 5;
    int lane = threadIdx.x & 31;
    if (row >= M) return;
    const float* w = W + (size_t)row * K;
    float acc[16];
#pragma unroll
    for (int b2 = 0; b2 < 16; b2++) acc[b2] = 0.f;
    for (int k = lane * 4; k < K; k += 128) {
        float4 wv = *(const float4*)(w + k);
#pragma unroll
        for (int b2 = 0; b2 < 16; b2++) {
            float4 av = *(const float4*)(sA + b2 * K + k);
            acc[b2] += wv.x * av.x + wv.y * av.y + wv.z * av.z + wv.w * av.w;
        }
    }
#pragma unroll
    for (int b2 = 0; b2 < 16; b2++) {
#pragma unroll
        for (int o = 16; o > 0; o >>= 1) acc[b2] += __shfl_xor_sync(0xffffffffu, acc[b2], o);
    }
    if (lane == 0) {
        const float inv = rsqrtf(1.f + 1e-5f);
#pragma unroll
        for (int b2 = 0; b2 < 16; b2++) {
            float t = acc[b2] + bias[row];
            if (EPI) {
                t = t >= 0.f ? t : pr[row] * t;
                t = t * inv * bg[row] + bb[row];
            }
            C[(size_t)b2 * M + row] = t;
        }
    }
}

// ---- lin2 (32768x1024, HBM-bound) fused with output scatter-add -----------
__global__ void k_lin2_out(const float* __restrict__ W,
                           const float* __restrict__ bias,
                           const float* __restrict__ pr,
                           const float* __restrict__ bg,
                           const float* __restrict__ bb,
                           const float* __restrict__ wo,
                           float* __restrict__ out,
                           int nrows) {
    int warp = (blockIdx.x * blockDim.x + threadIdx.x) >> 5;
    int lane = threadIdx.x & 31;
    int m0 = warp * 2;
    if (m0 >= nrows) return;
    float acc0[16], acc1[16];
#pragma unroll
    for (int b2 = 0; b2 < 16; b2++) { acc0[b2] = 0.f; acc1[b2] = 0.f; }

    const float* w0 = W + (size_t)m0 * MM1;
    const float* w1 = w0 + MM1;
    for (int k = lane * 4; k < MM1; k += 128) {
        float4 wv0 = *(const float4*)(w0 + k);
        float4 wv1 = *(const float4*)(w1 + k);
#pragma unroll
        for (int b2 = 0; b2 < 16; b2++) {
            float4 av = *(const float4*)(g_o1 + (size_t)b2 * MM1 + k);
            acc0[b2] += wv0.x * av.x + wv0.y * av.y + wv0.z * av.z + wv0.w * av.w;
            acc1[b2] += wv1.x * av.x + wv1.y * av.y + wv1.z * av.z + wv1.w * av.w;
        }
    }
    const float inv = rsqrtf(1.f + 1e-5f);
    int n0 = m0 >> 3, j0 = m0 & 7;
    int n1 = (m0 + 1) >> 3, j1 = (m0 + 1) & 7;
#pragma unroll
    for (int b2 = 0; b2 < 16; b2++) {
        float v0 = acc0[b2], v1 = acc1[b2];
#pragma unroll
        for (int o = 16; o > 0; o >>= 1) {
            v0 += __shfl_xor_sync(0xffffffffu, v0, o);
            v1 += __shfl_xor_sync(0xffffffffu, v1, o);
        }
        if (lane == 0) {
            float t0 = v0 + bias[m0];
            t0 = t0 >= 0.f ? t0 : pr[m0] * t0;
            t0 = t0 * inv * bg[m0] + bb[m0];
            float t1 = v1 + bias[m0 + 1];
            t1 = t1 >= 0.f ? t1 : pr[m0 + 1] * t1;
            t1 = t1 * inv * bg[m0 + 1] + bb[m0 + 1];
            size_t ob = (size_t)b2 * NN;
            atomicAdd(&out[(ob + n0) * 3 + 0], wo[j0] * t0);
            atomicAdd(&out[(ob + n0) * 3 + 1], wo[40 + j0] * t0);
            atomicAdd(&out[(ob + n0) * 3 + 2], wo[80 + j0] * t0);
            atomicAdd(&out[(ob + n1) * 3 + 0], wo[j1] * t1);
            atomicAdd(&out[(ob + n1) * 3 + 1], wo[40 + j1] * t1);
            atomicAdd(&out[(ob + n1) * 3 + 2], wo[80 + j1] * t1);
        }
    }
}

// ---------------- init y with output bias -----------------------------------
__global__ void k_init_out(const float* __restrict__ bo, float* __restrict__ out,
                           int nwork) {
    int i = blockIdx.x * blockDim.x + threadIdx.x;
    if (i < nwork) out[i] = bo[i % 3];
}

// ---------------- GRU combine ----------------------------------------------
__global__ void k_combine(const float* __restrict__ hidden, float* __restrict__ out,
                          int write_out, int nwork) {
    int t = blockIdx.x * blockDim.x + threadIdx.x;
    if (t >= nwork) return;
    int b = t / HH, j = t % HH;
    size_t base = (size_t)b * 3 * HH;
    float ir = g_gi[base + j], iz = g_gi[base + HH + j], in_ = g_gi[base + 2 * HH + j];
    float hr = g_gh[base + j], hz = g_gh[base + HH + j], hn = g_gh[base + 2 * HH + j];
    float r = 1.f / (1.f + expf(-(ir + hr)));
    float z = 1.f / (1.f + expf(-(iz + hz)));
    float n = tanhf(in_ + r * hn);
    float hp = hidden[(size_t)b * HH + j];
    float nh = (1.f - z) * n + z * hp;
    g_nh[(size_t)b * HH + j] = nh;
    if (write_out) out[(size_t)BB * NN * 3 + (size_t)b * HH + j] = nh;
}

// ---------------- launch ----------------------------------------------------
extern "C" void kernel_launch(void* const* d_in, const int* in_sizes, int n_in,
                              void* d_out, int out_size) {
    const float* x      = (const float*)d_in[0];
    const float* svp    = (const float*)d_in[1];
    const float* hidden = (const float*)d_in[2];
    const int*   ei     = (const int*)  d_in[3];
    const float* W0     = (const float*)d_in[4];
    const float* a0s    = (const float*)d_in[5];
    const float* a0d    = (const float*)d_in[6];
    const float* b0     = (const float*)d_in[7];
    const float* W1     = (const float*)d_in[8];
    const float* a1s    = (const float*)d_in[9];
    const float* a1d    = (const float*)d_in[10];
    const float* b1     = (const float*)d_in[11];
    const float* w_ih   = (const float*)d_in[12];
    const float* w_hh   = (const float*)d_in[13];
    const float* b_ih   = (const float*)d_in[14];
    const float* b_hh   = (const float*)d_in[15];
    const float* l1w    = (const float*)d_in[16];
    const float* l1b    = (const float*)d_in[17];
    const float* pr1    = (const float*)d_in[18];
    const float* bg1    = (const float*)d_in[19];
    const float* bb1    = (const float*)d_in[20];
    const float* l2w    = (const float*)d_in[21];
    const float* l2b    = (const float*)d_in[22];
    const float* pr2    = (const float*)d_in[23];
    const float* bg2    = (const float*)d_in[24];
    const float* bb2    = (const float*)d_in[25];
    const float* wo     = (const float*)d_in[26];
    const float* bo     = (const float*)d_in[27];
    float* out = (float*)d_out;

    int write_nh = (out_size >= BB * NN * 3 + BB * HH) ? 1 : 0;
    int warp_blks = (BB * NN) / 8;   // warp-per-(b,n) kernels, 8 warps/block

    // CSR build
    k_zero_deg<<<(NN + 255) / 256, 256>>>(NN);
    k_hist<<<(EE + 255) / 256, 256>>>(ei, EE);
    k_scan<<<1, 1024>>>(1);
    k_scatter<<<(EE + 255) / 256, 256>>>(ei, EE);

    // y = bo (lin2 scatter-add and GAT epilogue accumulate on top)
    k_init_out<<<(BB * NN * 3 + 255) / 256, 256>>>(bo, out, BB * NN * 3);

    // GRU -> nh -> lin1 -> lin2 (+ scatter-add into y)
    k_rowgemm<false><<<(3 * HH + 7) / 8, 256, 16 * 256 * 4>>>(
        x, 0, 0, w_ih, b_ih, nullptr, nullptr, nullptr, 3 * HH, 256);
    k_rowgemm<false><<<(3 * HH + 7) / 8, 256, 16 * 512 * 4>>>(
        hidden, 0, 1, w_hh, b_hh, nullptr, nullptr, nullptr, 3 * HH, 512);
    k_combine<<<(BB * HH + 255) / 256, 256>>>(hidden, out, write_nh, BB * HH);
    k_rowgemm<true><<<(MM1 + 7) / 8, 256, 16 * 512 * 4>>>(
        nullptr, 1, 2, l1w, l1b, pr1, bg1, bb1, MM1, 512);
    k_lin2_out<<<(MM2 / 2 + 7) / 8, 256>>>(l2w, l2b, pr2, bg2, bb2, wo, out, MM2);

    // GAT (all batches per launch)
    k_feat3<<<warp_blks, 256>>>(svp, W0, a0s, a0d, BB * NN);
    k_wgt<0><<<warp_blks, 256>>>(BB * NN);
    k_agg0_feat1<<<warp_blks, 256>>>(b0, W1, a1s, a1d, BB * NN);
    k_wgt<1><<<warp_blks, 256>>>(BB * NN);
    k_agg1_out<<<warp_blks, 256>>>(b1, wo, out, BB * NN);
}

// round 10
// speedup vs baseline: 1.1622x; 1.1622x over previous
#include <cuda_runtime.h>
#include <math.h>

#define BB   16
#define NN   4096
#define EE   65536
#define HH   512
#define MM1  1024
#define MM2  32768

// ---- device scratch. NEVER named in host code (host shadows + ATS would
// silently write host memory and trip the harness mem guard). ---------------
__device__ int   g_deg[NN];
__device__ int   g_off[NN + 1];
__device__ int   g_cur[NN];
__device__ int   g_src[EE];
__device__ float g_hA [(size_t)BB * NN * 32];   // 8 MB
__device__ float g_hB [(size_t)BB * NN * 32];   // 8 MB
__device__ float g_as0[(size_t)BB * NN], g_ad0[(size_t)BB * NN];
__device__ float g_as1[(size_t)BB * NN], g_ad1[(size_t)BB * NN];
__device__ float g_gi [(size_t)BB * 3 * HH];
__device__ float g_gh [(size_t)BB * 3 * HH];
__device__ float g_nh [(size_t)BB * HH];
__device__ float g_o1 [(size_t)BB * MM1];

// ---------------- CSR build ------------------------------------------------
__global__ void k_zero_deg(int n) {
    int i = blockIdx.x * blockDim.x + threadIdx.x;
    if (i < n) g_deg[i] = 0;
}
__global__ void k_hist(const int* __restrict__ ei, int n) {
    int i = blockIdx.x * blockDim.x + threadIdx.x;
    if (i < n) atomicAdd(&g_deg[ei[EE + i]], 1);
}
__global__ void k_scan(int active) {
    if (!active) return;
    __shared__ int s[1024];
    int tid = threadIdx.x;
    int b4 = tid * 4;
    int v0 = g_deg[b4], v1 = g_deg[b4 + 1], v2 = g_deg[b4 + 2], v3 = g_deg[b4 + 3];
    int sum = v0 + v1 + v2 + v3;
    s[tid] = sum;
    __syncthreads();
    for (int o = 1; o < 1024; o <<= 1) {
        int t = (tid >= o) ? s[tid - o] : 0;
        __syncthreads();
        s[tid] += t;
        __syncthreads();
    }
    int excl = s[tid] - sum;
    int o0 = excl, o1 = excl + v0, o2 = o1 + v1, o3 = o2 + v2;
    g_off[b4] = o0; g_off[b4 + 1] = o1; g_off[b4 + 2] = o2; g_off[b4 + 3] = o3;
    g_cur[b4] = o0; g_cur[b4 + 1] = o1; g_cur[b4 + 2] = o2; g_cur[b4 + 3] = o3;
    if (tid == 1023) g_off[NN] = s[1023];
}
__global__ void k_scatter(const int* __restrict__ ei, int n) {
    int i = blockIdx.x * blockDim.x + threadIdx.x;
    if (i < n) {
        int d = ei[EE + i];
        int pos = atomicAdd(&g_cur[d], 1);
        g_src[pos] = ei[i];
    }
}

__device__ __forceinline__ float lrelu(float v) { return v >= 0.f ? v : 0.2f * v; }

// ---- layer-0 features, all batches: warp per (b,n), lane = feature --------
__global__ void k_feat3(const float* __restrict__ svp,
                        const float* __restrict__ W0,
                        const float* __restrict__ a0s,
                        const float* __restrict__ a0d,
                        int nwork) {
    int gw = (blockIdx.x * blockDim.x + threadIdx.x) >> 5;
    int lane = threadIdx.x & 31;
    if (gw >= nwork) return;
    const float* xv = svp + (size_t)gw * 3;
    float v0 = xv[0], v1 = xv[1], v2 = xv[2];
    float hv = W0[lane * 3] * v0 + W0[lane * 3 + 1] * v1 + W0[lane * 3 + 2] * v2;
    g_hA[(size_t)gw * 32 + lane] = hv;
    float ps = hv * a0s[lane];
    float pd = hv * a0d[lane];
#pragma unroll
    for (int o = 16; o > 0; o >>= 1) {
        ps += __shfl_xor_sync(0xffffffffu, ps, o);
        pd += __shfl_xor_sync(0xffffffffu, pd, o);
    }
    if (lane == 0) { g_as0[gw] = ps; g_ad0[gw] = pd; }
}

// ---- fused softmax + aggregate (edge weights in registers, shfl-broadcast).
// Returns per-lane feature of the GAT output (lane = feature).
template <int LAYER>
__device__ __forceinline__ float gat_aggregate(int gw, int lane, int b, int d) {
    const float* as_ = (LAYER == 0) ? g_as0 : g_as1;
    const float* ad_ = (LAYER == 0) ? g_ad0 : g_ad1;
    const float* hsrc = (LAYER == 0) ? g_hA : g_hB;
    const float* asb = as_ + (size_t)b * NN;
    const float* hb = hsrc + (size_t)b * NN * 32;
    float add = ad_[gw];
    int beg = g_off[d], end = g_off[d + 1];

    // pass 1: segment max
    float e_self = lrelu(asb[d] + add);
    float m = e_self;
    for (int i = beg + lane; i < end; i += 32)
        m = fmaxf(m, lrelu(asb[g_src[i]] + add));
#pragma unroll
    for (int o = 16; o > 0; o >>= 1) m = fmaxf(m, __shfl_xor_sync(0xffffffffu, m, o));

    // pass 2: weights in registers per 32-edge chunk, broadcast via shfl
    float wself = expf(e_self - m);
    float wpart = (lane == 0) ? wself : 0.f;
    float acc = wself * hb[(size_t)d * 32 + lane];
    for (int base = beg; base < end; base += 32) {
        int nrem = end - base;
        int cnt = nrem < 32 ? nrem : 32;
        int s = (lane < cnt) ? g_src[base + lane] : d;
        float w = (lane < cnt) ? expf(lrelu(asb[s] + add) - m) : 0.f;
        wpart += w;
        for (int k = 0; k < cnt; k++) {
            float wk = __shfl_sync(0xffffffffu, w, k);
            int   sk = __shfl_sync(0xffffffffu, s, k);
            acc += wk * hb[(size_t)sk * 32 + lane];
        }
    }
#pragma unroll
    for (int o = 16; o > 0; o >>= 1) wpart += __shfl_xor_sync(0xffffffffu, wpart, o);
    return acc / wpart;
}

// ---- aggregate layer 0 fused with layer-1 feature transform ---------------
__global__ void k_agg0_feat1(const float* __restrict__ b0,
                             const float* __restrict__ W1,
                             const float* __restrict__ a1s,
                             const float* __restrict__ a1d,
                             int nwork) {
    int gw = (blockIdx.x * blockDim.x + threadIdx.x) >> 5;
    int lane = threadIdx.x & 31;
    if (gw >= nwork) return;
    int b = gw >> 12;
    int d = gw & (NN - 1);

    float gat = gat_aggregate<0>(gw, lane, b, d) + b0[lane];

    // layer-1 transform: h1[lane] = sum_k W1[lane][k] * gat_k
    float hv = 0.f;
#pragma unroll
    for (int k = 0; k < 32; k++) {
        float gk = __shfl_sync(0xffffffffu, gat, k);
        hv += W1[lane * 32 + k] * gk;
    }
    g_hB[(size_t)gw * 32 + lane] = hv;
    float ps = hv * a1s[lane];
    float pd = hv * a1d[lane];
#pragma unroll
    for (int o = 16; o > 0; o >>= 1) {
        ps += __shfl_xor_sync(0xffffffffu, ps, o);
        pd += __shfl_xor_sync(0xffffffffu, pd, o);
    }
    if (lane == 0) { g_as1[gw] = ps; g_ad1[gw] = pd; }
}

// ---- aggregate layer 1 fused with output projection; STORES out = bo + GAT
// slice (runs before lin2's atomic accumulation). ---------------------------
__global__ void k_agg1_out(const float* __restrict__ b1,
                           const float* __restrict__ wo,   // [3 x 40]
                           const float* __restrict__ bo,   // [3]
                           float* __restrict__ out,
                           int nwork) {
    int gw = (blockIdx.x * blockDim.x + threadIdx.x) >> 5;
    int lane = threadIdx.x & 31;
    if (gw >= nwork) return;
    int b = gw >> 12;
    int d = gw & (NN - 1);

    float gat = gat_aggregate<1>(gw, lane, b, d) + b1[lane];

    float s0 = gat * wo[8 + lane];
    float s1 = gat * wo[48 + lane];
    float s2 = gat * wo[88 + lane];
#pragma unroll
    for (int o = 16; o > 0; o >>= 1) {
        s0 += __shfl_xor_sync(0xffffffffu, s0, o);
        s1 += __shfl_xor_sync(0xffffffffu, s1, o);
        s2 += __shfl_xor_sync(0xffffffffu, s2, o);
    }
    if (lane == 0) {
        size_t base = (size_t)gw * 3;
        out[base + 0] = bo[0] + s0;
        out[base + 1] = bo[1] + s1;
        out[base + 2] = bo[2] + s2;
    }
}

// ---------------- small GEMMs: scratch chosen by selectors ------------------
// asel: 0 = external A arg, 1 = g_nh. csel: 0 = g_gi, 1 = g_gh, 2 = g_o1.
template <bool EPI>
__global__ void k_rowgemm(const float* __restrict__ Aext, int asel, int csel,
                          const float* __restrict__ W,
                          const float* __restrict__ bias,
                          const float* __restrict__ pr,
                          const float* __restrict__ bg,
                          const float* __restrict__ bb,
                          int M, int K) {
    const float* A = (asel == 1) ? (const float*)g_nh : Aext;
    float* C = (csel == 0) ? g_gi : (csel == 1) ? g_gh : g_o1;
    extern __shared__ float sA[];
    for (int i = threadIdx.x; i < 16 * K; i += blockDim.x) sA[i] = A[i];
    __syncthreads();
    int row = (blockIdx.x * blockDim.x + threadIdx.x) >> 5;
    int lane = threadIdx.x & 31;
    if (row >= M) return;
    const float* w = W + (size_t)row * K;
    float acc[16];
#pragma unroll
    for (int b2 = 0; b2 < 16; b2++) acc[b2] = 0.f;
    for (int k = lane * 4; k < K; k += 128) {
        float4 wv = *(const float4*)(w + k);
#pragma unroll
        for (int b2 = 0; b2 < 16; b2++) {
            float4 av = *(const float4*)(sA + b2 * K + k);
            acc[b2] += wv.x * av.x + wv.y * av.y + wv.z * av.z + wv.w * av.w;
        }
    }
#pragma unroll
    for (int b2 = 0; b2 < 16; b2++) {
#pragma unroll
        for (int o = 16; o > 0; o >>= 1) acc[b2] += __shfl_xor_sync(0xffffffffu, acc[b2], o);
    }
    if (lane == 0) {
        const float inv = rsqrtf(1.f + 1e-5f);
#pragma unroll
        for (int b2 = 0; b2 < 16; b2++) {
            float t = acc[b2] + bias[row];
            if (EPI) {
                t = t >= 0.f ? t : pr[row] * t;
                t = t * inv * bg[row] + bb[row];
            }
            C[(size_t)b2 * M + row] = t;
        }
    }
}

// ---- lin2 (32768x1024, HBM-bound): 4 rows/warp, streaming weights,
// lane-parallel epilogue scatter-add into out. ------------------------------
__global__ void k_lin2_out(const float* __restrict__ W,
                           const float* __restrict__ bias,
                           const float* __restrict__ pr,
                           const float* __restrict__ bg,
                           const float* __restrict__ bb,
                           const float* __restrict__ wo,
                           float* __restrict__ out,
                           int nrows) {
    int warp = (blockIdx.x * blockDim.x + threadIdx.x) >> 5;
    int lane = threadIdx.x & 31;
    int m0 = warp * 4;
    if (m0 >= nrows) return;
    float acc[4][16];
#pragma unroll
    for (int r = 0; r < 4; r++)
#pragma unroll
        for (int b2 = 0; b2 < 16; b2++) acc[r][b2] = 0.f;

    const float* wr = W + (size_t)m0 * MM1;
    for (int k = lane * 4; k < MM1; k += 128) {
        float4 wv0 = __ldcs((const float4*)(wr + k));
        float4 wv1 = __ldcs((const float4*)(wr + MM1 + k));
        float4 wv2 = __ldcs((const float4*)(wr + 2 * MM1 + k));
        float4 wv3 = __ldcs((const float4*)(wr + 3 * MM1 + k));
#pragma unroll
        for (int b2 = 0; b2 < 16; b2++) {
            float4 av = *(const float4*)(g_o1 + (size_t)b2 * MM1 + k);
            acc[0][b2] += wv0.x * av.x + wv0.y * av.y + wv0.z * av.z + wv0.w * av.w;
            acc[1][b2] += wv1.x * av.x + wv1.y * av.y + wv1.z * av.z + wv1.w * av.w;
            acc[2][b2] += wv2.x * av.x + wv2.y * av.y + wv2.z * av.z + wv2.w * av.w;
            acc[3][b2] += wv3.x * av.x + wv3.y * av.y + wv3.z * av.z + wv3.w * av.w;
        }
    }
    // reduce: full butterfly so every lane has the sum; lane b2 keeps batch b2
    float mine[4];
#pragma unroll
    for (int r = 0; r < 4; r++) {
        mine[r] = 0.f;
#pragma unroll
        for (int b2 = 0; b2 < 16; b2++) {
            float v = acc[r][b2];
#pragma unroll
            for (int o = 16; o > 0; o >>= 1) v += __shfl_xor_sync(0xffffffffu, v, o);
            if (lane == b2) mine[r] = v;
        }
    }
    if (lane < 16) {
        const float inv = rsqrtf(1.f + 1e-5f);
        size_t ob = (size_t)lane * NN;
#pragma unroll
        for (int r = 0; r < 4; r++) {
            int mrow = m0 + r;
            float t = mine[r] + bias[mrow];
            t = t >= 0.f ? t : pr[mrow] * t;
            t = t * inv * bg[mrow] + bb[mrow];
            int n = mrow >> 3, j = mrow & 7;
            atomicAdd(&out[(ob + n) * 3 + 0], wo[j] * t);
            atomicAdd(&out[(ob + n) * 3 + 1], wo[40 + j] * t);
            atomicAdd(&out[(ob + n) * 3 + 2], wo[80 + j] * t);
        }
    }
}

// ---------------- GRU combine ----------------------------------------------
__global__ void k_combine(const float* __restrict__ hidden, float* __restrict__ out,
                          int write_out, int nwork) {
    int t = blockIdx.x * blockDim.x + threadIdx.x;
    if (t >= nwork) return;
    int b = t / HH, j = t % HH;
    size_t base = (size_t)b * 3 * HH;
    float ir = g_gi[base + j], iz = g_gi[base + HH + j], in_ = g_gi[base + 2 * HH + j];
    float hr = g_gh[base + j], hz = g_gh[base + HH + j], hn = g_gh[base + 2 * HH + j];
    float r = 1.f / (1.f + expf(-(ir + hr)));
    float z = 1.f / (1.f + expf(-(iz + hz)));
    float n = tanhf(in_ + r * hn);
    float hp = hidden[(size_t)b * HH + j];
    float nh = (1.f - z) * n + z * hp;
    g_nh[(size_t)b * HH + j] = nh;
    if (write_out) out[(size_t)BB * NN * 3 + (size_t)b * HH + j] = nh;
}

// ---------------- launch ----------------------------------------------------
extern "C" void kernel_launch(void* const* d_in, const int* in_sizes, int n_in,
                              void* d_out, int out_size) {
    const float* x      = (const float*)d_in[0];
    const float* svp    = (const float*)d_in[1];
    const float* hidden = (const float*)d_in[2];
    const int*   ei     = (const int*)  d_in[3];
    const float* W0     = (const float*)d_in[4];
    const float* a0s    = (const float*)d_in[5];
    const float* a0d    = (const float*)d_in[6];
    const float* b0     = (const float*)d_in[7];
    const float* W1     = (const float*)d_in[8];
    const float* a1s    = (const float*)d_in[9];
    const float* a1d    = (const float*)d_in[10];
    const float* b1     = (const float*)d_in[11];
    const float* w_ih   = (const float*)d_in[12];
    const float* w_hh   = (const float*)d_in[13];
    const float* b_ih   = (const float*)d_in[14];
    const float* b_hh   = (const float*)d_in[15];
    const float* l1w    = (const float*)d_in[16];
    const float* l1b    = (const float*)d_in[17];
    const float* pr1    = (const float*)d_in[18];
    const float* bg1    = (const float*)d_in[19];
    const float* bb1    = (const float*)d_in[20];
    const float* l2w    = (const float*)d_in[21];
    const float* l2b    = (const float*)d_in[22];
    const float* pr2    = (const float*)d_in[23];
    const float* bg2    = (const float*)d_in[24];
    const float* bb2    = (const float*)d_in[25];
    const float* wo     = (const float*)d_in[26];
    const float* bo     = (const float*)d_in[27];
    float* out = (float*)d_out;

    int write_nh = (out_size >= BB * NN * 3 + BB * HH) ? 1 : 0;
    int warp_blks = (BB * NN) / 8;   // warp-per-(b,n) kernels, 8 warps/block

    // CSR build
    k_zero_deg<<<(NN + 255) / 256, 256>>>(NN);
    k_hist<<<(EE + 255) / 256, 256>>>(ei, EE);
    k_scan<<<1, 1024>>>(1);
    k_scatter<<<(EE + 255) / 256, 256>>>(ei, EE);

    // GAT (2 fused kernels); k_agg1_out STORES out = bo + GAT projection
    k_feat3<<<warp_blks, 256>>>(svp, W0, a0s, a0d, BB * NN);
    k_agg0_feat1<<<warp_blks, 256>>>(b0, W1, a1s, a1d, BB * NN);
    k_agg1_out<<<warp_blks, 256>>>(b1, wo, bo, out, BB * NN);

    // GRU -> nh -> lin1 -> lin2 (atomic accumulate into out)
    k_rowgemm<false><<<(3 * HH + 7) / 8, 256, 16 * 256 * 4>>>(
        x, 0, 0, w_ih, b_ih, nullptr, nullptr, nullptr, 3 * HH, 256);
    k_rowgemm<false><<<(3 * HH + 7) / 8, 256, 16 * 512 * 4>>>(
        hidden, 0, 1, w_hh, b_hh, nullptr, nullptr, nullptr, 3 * HH, 512);
    k_combine<<<(BB * HH + 255) / 256, 256>>>(hidden, out, write_nh, BB * HH);
    k_rowgemm<true><<<(MM1 + 7) / 8, 256, 16 * 512 * 4>>>(
        nullptr, 1, 2, l1w, l1b, pr1, bg1, bb1, MM1, 512);
    k_lin2_out<<<(MM2 / 4 + 7) / 8, 256>>>(l2w, l2b, pr2, bg2, bb2, wo, out, MM2);
}